// round 5
// baseline (speedup 1.0000x reference)
#include <cuda_runtime.h>
#include <math.h>
#include <stdint.h>

#define LLATT 16
#define UU    512
#define NB    4            // batches per group
#define CL    2            // CTAs per cluster (unit split)
#define USL   256          // units per CTA
#define NTHR  256
#define NGRP  64
#define NCTA  128

typedef unsigned long long ull;

struct SM {
    ull   hbuf[2][UU][2];        // [buf][global unit][bpair]       16 KB
    ull   states[8][UU][2];      // last 8 scan positions            64 KB
    ull   vrow[LLATT][USL][2];   // vertical term per column         64 KB
    ull   pred[4][USL][2];       // k-quarter partials               16 KB
    float winh[2][UU];
    float winv[2][UU];
    float wout[UU][2];
    float bcarry[UU];
    float z[NB][2];
    float logp[NB];
    float bout0, bout1;
    int   xs[NB][LLATT * LLATT];
    ull   bar1;
};

__device__ __forceinline__ ull pk2(float lo, float hi) {
    ull r; asm("mov.b64 %0, {%1, %2};" : "=l"(r) : "f"(lo), "f"(hi)); return r;
}
__device__ __forceinline__ void upk2(ull v, float& lo, float& hi) {
    asm("mov.b64 {%0, %1}, %2;" : "=f"(lo), "=f"(hi) : "l"(v));
}
__device__ __forceinline__ void fma2(ull& acc, ull a, ull b) {
    asm("fma.rn.f32x2 %0, %1, %2, %0;" : "+l"(acc) : "l"(a), "l"(b));
}
__device__ __forceinline__ ull add2(ull a, ull b) {
    ull r; asm("add.rn.f32x2 %0, %1, %2;" : "=l"(r) : "l"(a), "l"(b)); return r;
}
__device__ __forceinline__ uint32_t smem_u32(const void* p) {
    return (uint32_t)__cvta_generic_to_shared(p);
}
__device__ __forceinline__ uint32_t mapa_rank(uint32_t a, uint32_t r) {
    uint32_t o; asm("mapa.shared::cluster.u32 %0, %1, %2;" : "=r"(o) : "r"(a), "r"(r));
    return o;
}
__device__ __forceinline__ void st_cl64(uint32_t addr, ull v) {
    asm volatile("st.shared::cluster.b64 [%0], %1;" :: "r"(addr), "l"(v) : "memory");
}
__device__ __forceinline__ void mbar_init(uint32_t addr, uint32_t cnt) {
    asm volatile("mbarrier.init.shared.b64 [%0], %1;" :: "r"(addr), "r"(cnt) : "memory");
}
__device__ __forceinline__ void mbar_arrive_remote(uint32_t addr) {
    asm volatile("mbarrier.arrive.release.cluster.shared::cluster.b64 _, [%0];"
                 :: "r"(addr) : "memory");
}
__device__ __forceinline__ void mbar_wait_parity(uint32_t addr, uint32_t parity) {
    asm volatile(
        "{\n\t.reg .pred P;\n\t"
        "WLP_%=:\n\t"
        "mbarrier.try_wait.parity.acquire.cluster.shared::cta.b64 P, [%0], %1, 0x989680;\n\t"
        "@P bra.uni WDN_%=;\n\t"
        "bra.uni WLP_%=;\n\t"
        "WDN_%=:\n\t}"
        :: "r"(addr), "r"(parity) : "memory");
}
#define CLUSTER_ARRIVE() asm volatile("barrier.cluster.arrive.aligned;" ::: "memory")
#define CLUSTER_WAIT()   asm volatile("barrier.cluster.wait.aligned;"   ::: "memory")

// 64-k slice of the h-GEMV: acc[q][bp] += Wch[k][4 units] * h[k], prefetched
__device__ __forceinline__ void gemv64(ull acc[4][2], const float4* __restrict__ wp,
                                       const ull (*__restrict__ hb)[2], int kbase)
{
    float4 wb[2][8];
#pragma unroll
    for (int q = 0; q < 8; ++q) wb[0][q] = wp[(kbase + q) * 128];
#pragma unroll 1
    for (int kk = 0; kk < 64; kk += 8) {
        const int cb = (kk >> 3) & 1;
        if (kk + 8 < 64) {
#pragma unroll
            for (int q = 0; q < 8; ++q) wb[cb ^ 1][q] = wp[(kbase + kk + 8 + q) * 128];
        }
#pragma unroll
        for (int q = 0; q < 8; ++q) {
            const ulonglong2 hv = *(const ulonglong2*)&hb[kbase + kk + q][0];
            const float4 w = wb[cb][q];
            fma2(acc[0][0], hv.x, pk2(w.x, w.x)); fma2(acc[0][1], hv.y, pk2(w.x, w.x));
            fma2(acc[1][0], hv.x, pk2(w.y, w.y)); fma2(acc[1][1], hv.y, pk2(w.y, w.y));
            fma2(acc[2][0], hv.x, pk2(w.z, w.z)); fma2(acc[2][1], hv.y, pk2(w.z, w.z));
            fma2(acc[3][0], hv.x, pk2(w.w, w.w)); fma2(acc[3][1], hv.y, pk2(w.w, w.w));
        }
    }
}

__global__ void __launch_bounds__(NTHR, 1) __cluster_dims__(CL, 1, 1)
rnn2d_kernel(const int* __restrict__ x,
             const float* __restrict__ Winh, const float* __restrict__ Winv,
             const float* __restrict__ Wch,  const float* __restrict__ bch,
             const float* __restrict__ Wcv,
             const float* __restrict__ Wout, const float* __restrict__ bout,
             float* __restrict__ out)
{
    extern __shared__ char smraw[];
    SM& sm = *reinterpret_cast<SM*>(smraw);
    const int tid = threadIdx.x;
    uint32_t rank;
    asm("mov.u32 %0, %%cluster_ctarank;" : "=r"(rank));
    const int grp = blockIdx.x >> 1;

    // ---------------- prologue ----------------
    for (int idx = tid; idx < 2 * UU; idx += NTHR) {
        ((float*)sm.winh)[idx] = Winh[idx];
        ((float*)sm.winv)[idx] = Winv[idx];
        ((float*)sm.wout)[idx] = Wout[idx];
    }
    for (int idx = tid; idx < UU; idx += NTHR) sm.bcarry[idx] = bch[idx];
    for (int idx = tid; idx < NB * LLATT * LLATT; idx += NTHR)
        ((int*)sm.xs)[idx] = x[grp * NB * LLATT * LLATT + idx];
    if (tid < NB) sm.logp[tid] = 0.f;
    if (tid == 0) {
        sm.bout0 = bout[0]; sm.bout1 = bout[1];
        mbar_init(smem_u32(&sm.bar1), 256);
    }
    __syncthreads();
    CLUSTER_ARRIVE(); CLUSTER_WAIT();

    // h-GEMV mapping: tu4 -> 4 units, ks -> k-quarter (64 k per phase slice)
    const int ks  = tid >> 6;
    const int tu4 = tid & 63;
    const float4* __restrict__ WchP =
        reinterpret_cast<const float4*>(Wch) + (int)rank * 64 + tu4;
    // v-event mapping: tu2 -> 2 units, kh -> k-half
    const int kh  = tid >> 7;
    const int tu2 = tid & 127;
    const float2* __restrict__ WcvP =
        reinterpret_cast<const float2*>(Wcv) + (int)rank * 128 + tu2;

    const uint32_t bar_loc  = smem_u32(&sm.bar1);
    const uint32_t bar_rem  = mapa_rank(bar_loc, rank ^ 1u);
    const uint32_t hbuf_rem = mapa_rank(smem_u32(&sm.hbuf[0][0][0]), rank ^ 1u);
    const uint32_t st_rem   = mapa_rank(smem_u32(&sm.states[0][0][0]), rank ^ 1u);

    int n = 0, prev_i = -1, prev_c = -1;
    for (int i = 0; i < LLATT; ++i) {
        const int d = (i & 1) ? -1 : 1;
        for (int j = 0; j < LLATT; ++j, ++n) {
            const int c   = (d == 1) ? j : (LLATT - 1 - j);
            const int buf = n & 1;
            const int pb  = buf ^ 1;
            const bool evt = (j == 8 && i < 15) || (j == 0 && i > 0);
            bool prev_done = (n == 0);

            // "do_prev": wait peer slice of cell n-1, logits + logp for n-1
            #define DO_PREV() do {                                              \
                mbar_wait_parity(bar_loc, (uint32_t)((n - 1) & 1));              \
                {                                                                \
                    const int w = tid >> 5, lane = tid & 31;                     \
                    const int b = w >> 1, dc = w & 1;                            \
                    const int bp = b >> 1, hi = b & 1;                           \
                    float zz = 0.f;                                              \
                    _Pragma("unroll")                                            \
                    for (int q = 0; q < 16; ++q) {                               \
                        const int u = lane + q * 32;                             \
                        float lo2, hi2;                                          \
                        upk2(sm.hbuf[pb][u][bp], lo2, hi2);                      \
                        zz += (hi ? hi2 : lo2) * sm.wout[u][dc];                 \
                    }                                                            \
                    _Pragma("unroll")                                            \
                    for (int off = 16; off; off >>= 1)                           \
                        zz += __shfl_down_sync(0xffffffffu, zz, off);            \
                    if (lane == 0) sm.z[b][dc] = zz;                             \
                }                                                                \
                __syncthreads();                                                 \
                if (tid < NB) {                                                  \
                    const float z0 = sm.z[tid][0] + sm.bout0;                    \
                    const float z1 = sm.z[tid][1] + sm.bout1;                    \
                    const int s = sm.xs[tid][prev_i * LLATT + prev_c];           \
                    const float m = fmaxf(z0, z1);                               \
                    const float lse = m + logf(expf(z0 - m) + expf(z1 - m));     \
                    sm.logp[tid] += (s ? z1 : z0) - lse;                         \
                }                                                                \
            } while (0)

            if (evt) {
                if (!prev_done) { DO_PREV(); prev_done = true; }
                // ---- 8-column vertical GEMM (reads states slots 0-7) ----
                const int i_src = (j == 8) ? i : i - 1;
                const int p0    = (j == 8) ? 0 : 8;
                ull A[8][2][2];
#pragma unroll
                for (int p = 0; p < 8; ++p)
#pragma unroll
                    for (int q = 0; q < 2; ++q) { A[p][q][0] = 0ull; A[p][q][1] = 0ull; }
                float2 wb[2][8];
#pragma unroll
                for (int q = 0; q < 8; ++q) wb[0][q] = WcvP[(kh * 256 + q) * 256];
#pragma unroll 1
                for (int kk = 0; kk < 256; kk += 8) {
                    const int cb = (kk >> 3) & 1;
                    if (kk + 8 < 256) {
#pragma unroll
                        for (int q = 0; q < 8; ++q)
                            wb[cb ^ 1][q] = WcvP[(kh * 256 + kk + 8 + q) * 256];
                    }
#pragma unroll
                    for (int q = 0; q < 8; ++q) {
                        const int k = kh * 256 + kk + q;
                        const float2 w = wb[cb][q];
                        const ull wx = pk2(w.x, w.x);
                        const ull wy = pk2(w.y, w.y);
#pragma unroll
                        for (int p = 0; p < 8; ++p) {
                            const ulonglong2 sv = *(const ulonglong2*)&sm.states[p][k][0];
                            fma2(A[p][0][0], sv.x, wx); fma2(A[p][0][1], sv.y, wx);
                            fma2(A[p][1][0], sv.x, wy); fma2(A[p][1][1], sv.y, wy);
                        }
                    }
                }
                const int lu0 = 2 * tu2;
                if (kh == 0) {
#pragma unroll
                    for (int p = 0; p < 8; ++p) {
                        const int col = (i_src & 1) ? 15 - (p0 + p) : (p0 + p);
                        sm.vrow[col][lu0][0] = A[p][0][0];
                        sm.vrow[col][lu0][1] = A[p][0][1];
                        sm.vrow[col][lu0 + 1][0] = A[p][1][0];
                        sm.vrow[col][lu0 + 1][1] = A[p][1][1];
                    }
                }
                __syncthreads();
                if (kh == 1) {
#pragma unroll
                    for (int p = 0; p < 8; ++p) {
                        const int col = (i_src & 1) ? 15 - (p0 + p) : (p0 + p);
                        sm.vrow[col][lu0][0] = add2(sm.vrow[col][lu0][0], A[p][0][0]);
                        sm.vrow[col][lu0][1] = add2(sm.vrow[col][lu0][1], A[p][0][1]);
                        sm.vrow[col][lu0 + 1][0] = add2(sm.vrow[col][lu0 + 1][0], A[p][1][0]);
                        sm.vrow[col][lu0 + 1][1] = add2(sm.vrow[col][lu0 + 1][1], A[p][1][1]);
                    }
                }
                __syncthreads();
                CLUSTER_ARRIVE(); CLUSTER_WAIT();
            }

            // ---- h-GEMV: phase A (local k), overlap exchange, phase B ----
            ull acc[4][2];
#pragma unroll
            for (int q = 0; q < 4; ++q) { acc[q][0] = 0ull; acc[q][1] = 0ull; }
            if (j > 0) gemv64(acc, WchP, sm.hbuf[pb], (int)rank * 256 + ks * 64);
            if (!prev_done) { DO_PREV(); prev_done = true; }
            if (j > 0) {
                gemv64(acc, WchP, sm.hbuf[pb], ((int)rank ^ 1) * 256 + ks * 64);
#pragma unroll
                for (int q = 0; q < 4; ++q) {
                    ulonglong2 t; t.x = acc[q][0]; t.y = acc[q][1];
                    *(ulonglong2*)&sm.pred[ks][4 * tu4 + q][0] = t;
                }
            }
            __syncthreads();   // S1

            // ---- finalize: 1 unit per thread ----
            {
                const int ul = tid;
                const int ug = (int)rank * USL + ul;
                ull a0 = 0ull, a1 = 0ull;
                if (j > 0) {
                    const ulonglong2 t0 = *(const ulonglong2*)&sm.pred[0][ul][0];
                    const ulonglong2 t1 = *(const ulonglong2*)&sm.pred[1][ul][0];
                    const ulonglong2 t2 = *(const ulonglong2*)&sm.pred[2][ul][0];
                    const ulonglong2 t3 = *(const ulonglong2*)&sm.pred[3][ul][0];
                    a0 = add2(add2(t0.x, t1.x), add2(t2.x, t3.x));
                    a1 = add2(add2(t0.y, t1.y), add2(t2.y, t3.y));
                }
                if (i > 0) {
                    const ulonglong2 vr = *(const ulonglong2*)&sm.vrow[c][ul][0];
                    a0 = add2(a0, vr.x); a1 = add2(a1, vr.y);
                }
                float v[NB];
                upk2(a0, v[0], v[1]); upk2(a1, v[2], v[3]);
                const float base = sm.bcarry[ug];
                int sh[NB], sv[NB];
                if (j > 0) {
                    const int cp = c - d;
#pragma unroll
                    for (int b = 0; b < NB; ++b) sh[b] = sm.xs[b][i * LLATT + cp];
                }
                if (i > 0) {
#pragma unroll
                    for (int b = 0; b < NB; ++b) sv[b] = sm.xs[b][(i - 1) * LLATT + c];
                }
#pragma unroll
                for (int b = 0; b < NB; ++b) {
                    float t = v[b] + base;
                    if (j > 0) t += sm.winh[sh[b]][ug];
                    if (i > 0) t += sm.winv[sv[b]][ug];
                    v[b] = t > 0.f ? t : expm1f(t);
                }
                const ull e0 = pk2(v[0], v[1]);
                const ull e1 = pk2(v[2], v[3]);
                const int slot = j & 7;
                sm.hbuf[buf][ug][0] = e0;    sm.hbuf[buf][ug][1] = e1;
                sm.states[slot][ug][0] = e0; sm.states[slot][ug][1] = e1;
                const uint32_t ho = (uint32_t)(((buf * UU + ug) * 2) * 8);
                st_cl64(hbuf_rem + ho,     e0);
                st_cl64(hbuf_rem + ho + 8, e1);
                const uint32_t so = (uint32_t)(((slot * UU + ug) * 2) * 8);
                st_cl64(st_rem + so,     e0);
                st_cl64(st_rem + so + 8, e1);
                mbar_arrive_remote(bar_rem);
            }
            __syncthreads();   // S2
            prev_i = i; prev_c = c;
        }
    }

    // epilogue: logits + logp for cell 255
    {
        const int pb = (n - 1) & 1;
        DO_PREV();
    }
    __syncthreads();
    if (rank == 0 && tid < NB) out[grp * NB + tid] = sm.logp[tid];
    CLUSTER_ARRIVE(); CLUSTER_WAIT();
}

extern "C" void kernel_launch(void* const* d_in, const int* in_sizes, int n_in,
                              void* d_out, int out_size)
{
    const int*   x    = (const int*)d_in[0];
    const float* Winh = (const float*)d_in[1];
    const float* Winv = (const float*)d_in[2];
    const float* Wch  = (const float*)d_in[3];
    const float* bch  = (const float*)d_in[4];
    const float* Wcv  = (const float*)d_in[5];
    const float* Wout = (const float*)d_in[6];
    const float* bout = (const float*)d_in[7];
    float* out = (float*)d_out;

    const int smem = (int)sizeof(SM);
    cudaFuncSetAttribute(rnn2d_kernel,
                         cudaFuncAttributeMaxDynamicSharedMemorySize, smem);
    rnn2d_kernel<<<NCTA, NTHR, smem>>>(x, Winh, Winv, Wch, bch, Wcv,
                                       Wout, bout, out);
}

// round 6
// speedup vs baseline: 1.0228x; 1.0228x over previous
#include <cuda_runtime.h>
#include <math.h>
#include <stdint.h>

#define LLATT 16
#define UU    512
#define NBAT  8            // batches per cluster group
#define BP    4            // batch pairs (ull of 2 f32)
#define CLS   4            // CTAs per cluster (unit split)
#define USL   128          // units per CTA
#define NTHR  256
#define NGRP  32
#define NCTA  128

typedef unsigned long long ull;

struct SM {
    ull   hbuf[2][UU][BP];       // full h, double buffered          32 KB
    ull   states[4][UU][BP];     // last 4 scan positions (full)     64 KB
    ull   vrow[LLATT][USL][BP];  // vertical term, local unit slice  64 KB
    ull   pred[8][USL][BP];      // h-GEMV k-slice partials          32 KB
    float winh[2][UU];
    float winv[2][UU];
    float wout[UU][2];
    float bcarry[UU];
    ull   zbox[CLS][NBAT];       // logit partials (z0,z1) packed
    float logp[NBAT];
    float bout0, bout1;
    int   xs[NBAT][LLATT * LLATT];
    ull   bar1;
};

__device__ __forceinline__ ull pk2(float lo, float hi) {
    ull r; asm("mov.b64 %0, {%1, %2};" : "=l"(r) : "f"(lo), "f"(hi)); return r;
}
__device__ __forceinline__ void upk2(ull v, float& lo, float& hi) {
    asm("mov.b64 {%0, %1}, %2;" : "=f"(lo), "=f"(hi) : "l"(v));
}
__device__ __forceinline__ void fma2(ull& acc, ull a, ull b) {
    asm("fma.rn.f32x2 %0, %1, %2, %0;" : "+l"(acc) : "l"(a), "l"(b));
}
__device__ __forceinline__ ull add2(ull a, ull b) {
    ull r; asm("add.rn.f32x2 %0, %1, %2;" : "=l"(r) : "l"(a), "l"(b)); return r;
}
__device__ __forceinline__ uint32_t smem_u32(const void* p) {
    return (uint32_t)__cvta_generic_to_shared(p);
}
__device__ __forceinline__ uint32_t mapa_rank(uint32_t a, uint32_t r) {
    uint32_t o; asm("mapa.shared::cluster.u32 %0, %1, %2;" : "=r"(o) : "r"(a), "r"(r));
    return o;
}
__device__ __forceinline__ void st_cl64(uint32_t addr, ull v) {
    asm volatile("st.shared::cluster.b64 [%0], %1;" :: "r"(addr), "l"(v) : "memory");
}
__device__ __forceinline__ void mbar_init(uint32_t addr, uint32_t cnt) {
    asm volatile("mbarrier.init.shared.b64 [%0], %1;" :: "r"(addr), "r"(cnt) : "memory");
}
__device__ __forceinline__ void mbar_arrive_remote(uint32_t addr) {
    asm volatile("mbarrier.arrive.release.cluster.shared::cluster.b64 _, [%0];"
                 :: "r"(addr) : "memory");
}
__device__ __forceinline__ void mbar_wait_parity(uint32_t addr, uint32_t parity) {
    asm volatile(
        "{\n\t.reg .pred P;\n\t"
        "WLP_%=:\n\t"
        "mbarrier.try_wait.parity.acquire.cluster.shared::cta.b64 P, [%0], %1, 0x989680;\n\t"
        "@P bra.uni WDN_%=;\n\t"
        "bra.uni WLP_%=;\n\t"
        "WDN_%=:\n\t}"
        :: "r"(addr), "r"(parity) : "memory");
}
#define CLUSTER_ARRIVE() asm volatile("barrier.cluster.arrive.aligned;" ::: "memory")
#define CLUSTER_WAIT()   asm volatile("barrier.cluster.wait.aligned;"   ::: "memory")

__global__ void __launch_bounds__(NTHR, 1) __cluster_dims__(CLS, 1, 1)
rnn2d_kernel(const int* __restrict__ x,
             const float* __restrict__ Winh, const float* __restrict__ Winv,
             const float* __restrict__ Wch,  const float* __restrict__ bch,
             const float* __restrict__ Wcv,
             const float* __restrict__ Wout, const float* __restrict__ bout,
             float* __restrict__ out)
{
    extern __shared__ char smraw[];
    SM& sm = *reinterpret_cast<SM*>(smraw);
    const int tid = threadIdx.x;
    uint32_t rank;
    asm("mov.u32 %0, %%cluster_ctarank;" : "=r"(rank));
    const int grp = blockIdx.x >> 2;

    // ---------------- prologue ----------------
    for (int idx = tid; idx < 2 * UU; idx += NTHR) {
        ((float*)sm.winh)[idx] = Winh[idx];
        ((float*)sm.winv)[idx] = Winv[idx];
        ((float*)sm.wout)[idx] = Wout[idx];
    }
    for (int idx = tid; idx < UU; idx += NTHR) sm.bcarry[idx] = bch[idx];
    for (int idx = tid; idx < NBAT * LLATT * LLATT; idx += NTHR)
        ((int*)sm.xs)[idx] = x[grp * NBAT * LLATT * LLATT + idx];
    if (tid < NBAT) sm.logp[tid] = 0.f;
    if (tid == 0) {
        sm.bout0 = bout[0]; sm.bout1 = bout[1];
        mbar_init(smem_u32(&sm.bar1), 3 * 128);   // 3 peers x 128 odd writers
    }
    __syncthreads();
    CLUSTER_ARRIVE(); CLUSTER_WAIT();

    // ---- per-thread mappings ----
    // h-GEMV: ks = k-slice (8 x 64k), tu4 -> 4 units
    const int ks  = tid >> 5;
    const int tu4 = tid & 31;
    const float4* __restrict__ WchP =
        reinterpret_cast<const float4*>(Wch) + (int)rank * 32 + tu4;
    // v-event: kq = k-quarter (4 x 128k), tu2 -> 2 units
    const int kq  = tid >> 6;
    const int tu2 = tid & 63;
    const float2* __restrict__ WcvP =
        reinterpret_cast<const float2*>(Wcv) + (int)rank * 64 + tu2;
    // finalize: ul = unit, bh = bpair half
    const int ul  = tid >> 1;
    const int bh  = tid & 1;
    const int bp0 = 2 * bh;
    const int ugf = (int)rank * USL + ul;

    // DSMEM addresses for the 3 peers
    uint32_t bar_rem[3], hbuf_rem[3], st_rem[3], zbox_rem[3];
    {
        const uint32_t bl = smem_u32(&sm.bar1);
        const uint32_t hb = smem_u32(&sm.hbuf[0][0][0]);
        const uint32_t sb = smem_u32(&sm.states[0][0][0]);
        const uint32_t zb = smem_u32(&sm.zbox[0][0]);
        int pi = 0;
        for (int r = 0; r < CLS; ++r) {
            if (r == (int)rank) continue;
            bar_rem[pi]  = mapa_rank(bl, (uint32_t)r);
            hbuf_rem[pi] = mapa_rank(hb, (uint32_t)r);
            st_rem[pi]   = mapa_rank(sb, (uint32_t)r);
            zbox_rem[pi] = mapa_rank(zb, (uint32_t)r);
            ++pi;
        }
    }
    const uint32_t bar_loc = smem_u32(&sm.bar1);

    int n = 0;
    for (int i = 0; i < LLATT; ++i) {
        const int d = (i & 1) ? -1 : 1;
        for (int j = 0; j < LLATT; ++j, ++n) {
            const int c   = (d == 1) ? j : (LLATT - 1 - j);
            const int buf = n & 1;
            const int pb  = buf ^ 1;
            const int slot = j & 3;

            // ---- vertical GEMM event: every 4 cells ----
            const bool evt = ((j & 3) == 0 || j == 4 || j == 8 || j == 12) &&
                             ((j & 3) == 0) &&
                             !(j == 0 && i == 0) && !(j != 0 && i == 15);
            if (evt) {
                __syncthreads();
                const int rsrc = (j == 0) ? i - 1 : i;
                const int p0   = (j == 0) ? 12 : j - 4;
                int col[4], slt[4];
#pragma unroll
                for (int p = 0; p < 4; ++p) {
                    const int pp = p0 + p;
                    col[p] = (rsrc & 1) ? (15 - pp) : pp;
                    slt[p] = pp & 3;
                }
                ull acc[4][2][4];    // [col][unit][bp]
#pragma unroll
                for (int p = 0; p < 4; ++p)
#pragma unroll
                    for (int u = 0; u < 2; ++u)
#pragma unroll
                        for (int b = 0; b < 4; ++b) acc[p][u][b] = 0ull;
                const int k0 = kq * 128;
                float2 wb[2][8];
#pragma unroll
                for (int q = 0; q < 8; ++q) wb[0][q] = WcvP[(k0 + q) * 256];
#pragma unroll 1
                for (int kk = 0; kk < 128; kk += 8) {
                    const int cb = (kk >> 3) & 1;
                    if (kk + 8 < 128) {
#pragma unroll
                        for (int q = 0; q < 8; ++q)
                            wb[cb ^ 1][q] = WcvP[(k0 + kk + 8 + q) * 256];
                    }
#pragma unroll
                    for (int q = 0; q < 8; ++q) {
                        const int k = k0 + kk + q;
                        const float2 w = wb[cb][q];
                        const ull wx = pk2(w.x, w.x);
                        const ull wy = pk2(w.y, w.y);
#pragma unroll
                        for (int p = 0; p < 4; ++p) {
                            const ulonglong2 s01 =
                                *(const ulonglong2*)&sm.states[slt[p]][k][0];
                            const ulonglong2 s23 =
                                *(const ulonglong2*)&sm.states[slt[p]][k][2];
                            fma2(acc[p][0][0], s01.x, wx); fma2(acc[p][0][1], s01.y, wx);
                            fma2(acc[p][0][2], s23.x, wx); fma2(acc[p][0][3], s23.y, wx);
                            fma2(acc[p][1][0], s01.x, wy); fma2(acc[p][1][1], s01.y, wy);
                            fma2(acc[p][1][2], s23.x, wy); fma2(acc[p][1][3], s23.y, wy);
                        }
                    }
                }
                const int lu = 2 * tu2;
#pragma unroll
                for (int q = 0; q < 4; ++q) {
                    if (kq == q) {
                        if (q == 0) {
#pragma unroll
                            for (int p = 0; p < 4; ++p)
#pragma unroll
                                for (int u = 0; u < 2; ++u) {
                                    ulonglong2 t0, t1;
                                    t0.x = acc[p][u][0]; t0.y = acc[p][u][1];
                                    t1.x = acc[p][u][2]; t1.y = acc[p][u][3];
                                    *(ulonglong2*)&sm.vrow[col[p]][lu + u][0] = t0;
                                    *(ulonglong2*)&sm.vrow[col[p]][lu + u][2] = t1;
                                }
                        } else {
#pragma unroll
                            for (int p = 0; p < 4; ++p)
#pragma unroll
                                for (int u = 0; u < 2; ++u) {
                                    ull* vp = &sm.vrow[col[p]][lu + u][0];
                                    vp[0] = add2(vp[0], acc[p][u][0]);
                                    vp[1] = add2(vp[1], acc[p][u][1]);
                                    vp[2] = add2(vp[2], acc[p][u][2]);
                                    vp[3] = add2(vp[3], acc[p][u][3]);
                                }
                        }
                    }
                    __syncthreads();
                }
                CLUSTER_ARRIVE(); CLUSTER_WAIT();   // fence event vs slot reuse
            }

            // ---- h @ W_carry_h: 8-way k-split, 4 units x 4 bp per thread ----
            if (j > 0) {
                ull acc[4][4];
#pragma unroll
                for (int u = 0; u < 4; ++u)
#pragma unroll
                    for (int b = 0; b < 4; ++b) acc[u][b] = 0ull;
                const int k0 = ks * 64;
                const ull (*__restrict__ hb)[BP] = sm.hbuf[pb];
                float4 wbuf[2][8];
#pragma unroll
                for (int q = 0; q < 8; ++q) wbuf[0][q] = WchP[(k0 + q) * 128];
#pragma unroll 1
                for (int kk = 0; kk < 64; kk += 8) {
                    const int cb = (kk >> 3) & 1;
                    if (kk + 8 < 64) {
#pragma unroll
                        for (int q = 0; q < 8; ++q)
                            wbuf[cb ^ 1][q] = WchP[(k0 + kk + 8 + q) * 128];
                    }
#pragma unroll
                    for (int q = 0; q < 8; ++q) {
                        const int k = k0 + kk + q;
                        const ulonglong2 h01 = *(const ulonglong2*)&hb[k][0];
                        const ulonglong2 h23 = *(const ulonglong2*)&hb[k][2];
                        const float4 w = wbuf[cb][q];
                        const ull w0 = pk2(w.x, w.x);
                        const ull w1 = pk2(w.y, w.y);
                        const ull w2 = pk2(w.z, w.z);
                        const ull w3 = pk2(w.w, w.w);
                        fma2(acc[0][0], h01.x, w0); fma2(acc[0][1], h01.y, w0);
                        fma2(acc[0][2], h23.x, w0); fma2(acc[0][3], h23.y, w0);
                        fma2(acc[1][0], h01.x, w1); fma2(acc[1][1], h01.y, w1);
                        fma2(acc[1][2], h23.x, w1); fma2(acc[1][3], h23.y, w1);
                        fma2(acc[2][0], h01.x, w2); fma2(acc[2][1], h01.y, w2);
                        fma2(acc[2][2], h23.x, w2); fma2(acc[2][3], h23.y, w2);
                        fma2(acc[3][0], h01.x, w3); fma2(acc[3][1], h01.y, w3);
                        fma2(acc[3][2], h23.x, w3); fma2(acc[3][3], h23.y, w3);
                    }
                }
#pragma unroll
                for (int u = 0; u < 4; ++u) {
                    ulonglong2 t0, t1;
                    t0.x = acc[u][0]; t0.y = acc[u][1];
                    t1.x = acc[u][2]; t1.y = acc[u][3];
                    *(ulonglong2*)&sm.pred[ks][4 * tu4 + u][0] = t0;
                    *(ulonglong2*)&sm.pred[ks][4 * tu4 + u][2] = t1;
                }
            }
            __syncthreads();   // S1

            // ---- finalize: unit ul, bpairs bp0..bp0+1 (4 batches) ----
            {
                ull a0 = 0ull, a1 = 0ull;
                if (j > 0) {
#pragma unroll
                    for (int s = 0; s < 8; ++s) {
                        const ulonglong2 t =
                            *(const ulonglong2*)&sm.pred[s][ul][bp0];
                        a0 = add2(a0, t.x); a1 = add2(a1, t.y);
                    }
                }
                if (i > 0) {
                    const ulonglong2 t = *(const ulonglong2*)&sm.vrow[c][ul][bp0];
                    a0 = add2(a0, t.x); a1 = add2(a1, t.y);
                }
                float v[4];
                upk2(a0, v[0], v[1]); upk2(a1, v[2], v[3]);
                const float base = sm.bcarry[ugf];
                const int bb0 = 4 * bh;
                int sh[4], sv[4];
                if (j > 0) {
                    const int cp = c - d;
#pragma unroll
                    for (int q = 0; q < 4; ++q) sh[q] = sm.xs[bb0 + q][i * LLATT + cp];
                }
                if (i > 0) {
#pragma unroll
                    for (int q = 0; q < 4; ++q) sv[q] = sm.xs[bb0 + q][(i - 1) * LLATT + c];
                }
#pragma unroll
                for (int q = 0; q < 4; ++q) {
                    float t = v[q] + base;
                    if (j > 0) t += sm.winh[sh[q]][ugf];
                    if (i > 0) t += sm.winv[sv[q]][ugf];
                    v[q] = t > 0.f ? t : expm1f(t);
                }
                const ull e0 = pk2(v[0], v[1]);
                const ull e1 = pk2(v[2], v[3]);
                sm.hbuf[buf][ugf][bp0]     = e0;
                sm.hbuf[buf][ugf][bp0 + 1] = e1;
                sm.states[slot][ugf][bp0]     = e0;
                sm.states[slot][ugf][bp0 + 1] = e1;
            }
            __syncthreads();   // S2: local h slice complete

            // ---- local logit partials: warp w = batch w, local 128 units ----
            float z0 = 0.f, z1 = 0.f;
            {
                const int w = tid >> 5, lane = tid & 31;
                const int bpair = w >> 1, hf = w & 1;
#pragma unroll
                for (int t = 0; t < 4; ++t) {
                    const int u = lane * 4 + t;
                    const int ug = (int)rank * USL + u;
                    float lo, hi;
                    upk2(sm.hbuf[buf][ug][bpair], lo, hi);
                    const float hv = hf ? hi : lo;
                    const float2 wo = *(const float2*)&sm.wout[ug][0];
                    z0 += hv * wo.x; z1 += hv * wo.y;
                }
#pragma unroll
                for (int off = 16; off; off >>= 1) {
                    z0 += __shfl_xor_sync(0xffffffffu, z0, off);
                    z1 += __shfl_xor_sync(0xffffffffu, z1, off);
                }
            }

            // ---- exchange: odd threads push slice + partial z, then arrive ----
            if (bh == 1) {
                const ull e0 = sm.hbuf[buf][ugf][0];   // partner's bp 0,1
                const ull e1 = sm.hbuf[buf][ugf][1];
                const ull f0 = sm.hbuf[buf][ugf][2];   // own bp 2,3
                const ull f1 = sm.hbuf[buf][ugf][3];
                const uint32_t ho = (uint32_t)(((buf * UU + ugf) * BP) * 8);
                const uint32_t so = (uint32_t)(((slot * UU + ugf) * BP) * 8);
#pragma unroll
                for (int pr = 0; pr < 3; ++pr) {
                    st_cl64(hbuf_rem[pr] + ho,      e0);
                    st_cl64(hbuf_rem[pr] + ho + 8,  e1);
                    st_cl64(hbuf_rem[pr] + ho + 16, f0);
                    st_cl64(hbuf_rem[pr] + ho + 24, f1);
                    st_cl64(st_rem[pr] + so,      e0);
                    st_cl64(st_rem[pr] + so + 8,  e1);
                    st_cl64(st_rem[pr] + so + 16, f0);
                    st_cl64(st_rem[pr] + so + 24, f1);
                }
                if ((tid & 31) == 1) {                 // lane 1: z partial
                    const int w = tid >> 5;
                    const ull zp = pk2(z0, z1);
                    sm.zbox[rank][w] = zp;
                    const uint32_t zo = (uint32_t)(((int)rank * NBAT + w) * 8);
#pragma unroll
                    for (int pr = 0; pr < 3; ++pr) st_cl64(zbox_rem[pr] + zo, zp);
                }
#pragma unroll
                for (int pr = 0; pr < 3; ++pr) mbar_arrive_remote(bar_rem[pr]);
            }
            __syncthreads();   // S3
            mbar_wait_parity(bar_loc, (uint32_t)(n & 1));

            // ---- log-prob accumulation (full z from 4 CTAs) ----
            if (tid < NBAT) {
                float zz0 = sm.bout0, zz1 = sm.bout1;
#pragma unroll
                for (int src = 0; src < CLS; ++src) {
                    float a, b;
                    upk2(sm.zbox[src][tid], a, b);
                    zz0 += a; zz1 += b;
                }
                const int s = sm.xs[tid][i * LLATT + c];
                const float m = fmaxf(zz0, zz1);
                const float lse = m + logf(expf(zz0 - m) + expf(zz1 - m));
                sm.logp[tid] += (s ? zz1 : zz0) - lse;
            }
        }
    }
    __syncthreads();
    if (rank == 0 && tid < NBAT) out[grp * NBAT + tid] = sm.logp[tid];
    CLUSTER_ARRIVE(); CLUSTER_WAIT();
}

extern "C" void kernel_launch(void* const* d_in, const int* in_sizes, int n_in,
                              void* d_out, int out_size)
{
    const int*   x    = (const int*)d_in[0];
    const float* Winh = (const float*)d_in[1];
    const float* Winv = (const float*)d_in[2];
    const float* Wch  = (const float*)d_in[3];
    const float* bch  = (const float*)d_in[4];
    const float* Wcv  = (const float*)d_in[5];
    const float* Wout = (const float*)d_in[6];
    const float* bout = (const float*)d_in[7];
    float* out = (float*)d_out;

    const int smem = (int)sizeof(SM);
    cudaFuncSetAttribute(rnn2d_kernel,
                         cudaFuncAttributeMaxDynamicSharedMemorySize, smem);
    rnn2d_kernel<<<NCTA, NTHR, smem>>>(x, Winh, Winv, Wch, bch, Wcv,
                                       Wout, bout, out);
}